// round 3
// baseline (speedup 1.0000x reference)
#include <cuda_runtime.h>

#define H_DIM 256
#define HH    128   // hidden = H/2
#define O_DIM 128
#define BM    128
#define BK    16
#define NEG_SLOPE 0.015f

// Scratch: segment sums of hidden activations [G, HH] and per-graph counts.
__device__ float g_hsum[1 << 21];
__device__ float g_counts[1 << 16];

static __device__ __forceinline__ unsigned long long pack2(float x, float y) {
    unsigned long long r;
    asm("mov.b64 %0, {%1,%2};" : "=l"(r) : "f"(x), "f"(y));
    return r;
}
static __device__ __forceinline__ void unpack2(unsigned long long v, float& x, float& y) {
    asm("mov.b64 {%0,%1}, %2;" : "=f"(x), "=f"(y) : "l"(v));
}
static __device__ __forceinline__ unsigned long long ffma2(unsigned long long a,
                                                           unsigned long long b,
                                                           unsigned long long c) {
    unsigned long long d;
    asm("fma.rn.f32x2 %0, %1, %2, %3;" : "=l"(d) : "l"(a), "l"(b), "l"(c));
    return d;
}

__global__ void zero_kernel(int hsumN, int G) {
    int i = blockIdx.x * blockDim.x + threadIdx.x;
    if (i < hsumN) g_hsum[i] = 0.f;
    if (i < G)     g_counts[i] = 0.f;
}

__global__ void count_kernel(const int* __restrict__ batch, int N) {
    int i = blockIdx.x * blockDim.x + threadIdx.x;
    if (i >= N) return;
    int b = batch[i];
    unsigned act = __activemask();
    unsigned m = __match_any_sync(act, b);
    int leader = __ffs(m) - 1;
    if ((int)(threadIdx.x & 31) == leader)
        atomicAdd(&g_counts[b], (float)__popc(m));
}

// Fused: h = LeakyReLU(v @ W1 + b1); segmented column-sum of h into g_hsum.
// Tile: BM=128 rows x HH=128 cols, K=256 in BK=16 chunks.
// 256 threads, each computes 8x8 outputs held as 8x4 packed f32x2 accumulators.
extern "C" __global__ void __launch_bounds__(256, 2)
fused1(const float* __restrict__ v, const int* __restrict__ batch,
       const float* __restrict__ W1, const float* __restrict__ b1, int N)
{
    extern __shared__ float smem[];
    const int AS = 132;                       // padded stride for A (k-major)
    float* As = smem;                          // [BK][AS]
    float* Bs = As + BK * AS;                  // [BK][HH]
    float* Os = Bs + BK * HH;                  // [BM][132] h tile (row-major)
    int*   sb = (int*)(Os + BM * 132);         // [BM] batch ids

    int t  = threadIdx.x;
    int tx = t & 15, ty = t >> 4;
    int tx8 = tx * 8, ty8 = ty * 8;
    long long r0 = (long long)blockIdx.x * BM;
    int valid = N - (int)r0; if (valid > BM) valid = BM;

    if (t < BM) sb[t] = (t < valid) ? batch[r0 + t] : -1;

    // Accumulators initialized with b1 (broadcast over rows)
    unsigned long long c[8][4];
#pragma unroll
    for (int jj = 0; jj < 4; jj++) {
        float2 bb = *(const float2*)(b1 + tx8 + jj * 2);
        unsigned long long p = pack2(bb.x, bb.y);
#pragma unroll
        for (int i = 0; i < 8; i++) c[i][jj] = p;
    }

    const float* vbase = v + r0 * H_DIM;
    for (int kt = 0; kt < H_DIM / BK; ++kt) {
        // Load A tile: 128 rows x 16 k -> As[k][row] (transposed scatter)
#pragma unroll
        for (int q = 0; q < 2; q++) {
            int idx = t * 2 + q;
            int row = idx >> 2, k4 = (idx & 3) * 4;
            int grow = (row < valid) ? row : (valid - 1);
            float4 a = *(const float4*)(vbase + (long long)grow * H_DIM + kt * BK + k4);
            As[(k4 + 0) * AS + row] = a.x;
            As[(k4 + 1) * AS + row] = a.y;
            As[(k4 + 2) * AS + row] = a.z;
            As[(k4 + 3) * AS + row] = a.w;
        }
        // Load B tile: W1[kt*16 .. +16, 0:128] contiguous
#pragma unroll
        for (int q = 0; q < 2; q++) {
            int idx = t * 2 + q;
            int kr = idx >> 5, c4 = (idx & 31) * 4;
            *(float4*)(Bs + kr * HH + c4) =
                *(const float4*)(W1 + (long long)(kt * BK + kr) * HH + c4);
        }
        __syncthreads();
#pragma unroll
        for (int kk = 0; kk < BK; ++kk) {
            float4 a0 = *(const float4*)(As + kk * AS + ty8);
            float4 a1 = *(const float4*)(As + kk * AS + ty8 + 4);
            ulonglong2 bA = *(const ulonglong2*)(Bs + kk * HH + tx8);
            ulonglong2 bB = *(const ulonglong2*)(Bs + kk * HH + tx8 + 4);
            unsigned long long bb0 = bA.x, bb1 = bA.y, bb2 = bB.x, bb3 = bB.y;
            float av[8] = {a0.x, a0.y, a0.z, a0.w, a1.x, a1.y, a1.z, a1.w};
#pragma unroll
            for (int i = 0; i < 8; i++) {
                unsigned long long ai = pack2(av[i], av[i]);
                c[i][0] = ffma2(ai, bb0, c[i][0]);
                c[i][1] = ffma2(ai, bb1, c[i][1]);
                c[i][2] = ffma2(ai, bb2, c[i][2]);
                c[i][3] = ffma2(ai, bb3, c[i][3]);
            }
        }
        __syncthreads();
    }

    // Epilogue: LeakyReLU, stage tile in smem
#pragma unroll
    for (int i = 0; i < 8; i++) {
        float o[8];
#pragma unroll
        for (int jj = 0; jj < 4; jj++) unpack2(c[i][jj], o[jj * 2], o[jj * 2 + 1]);
#pragma unroll
        for (int j = 0; j < 8; j++) { float x = o[j]; o[j] = (x >= 0.f) ? x : NEG_SLOPE * x; }
        *(float4*)(Os + (ty8 + i) * 132 + tx8)     = make_float4(o[0], o[1], o[2], o[3]);
        *(float4*)(Os + (ty8 + i) * 132 + tx8 + 4) = make_float4(o[4], o[5], o[6], o[7]);
    }
    __syncthreads();

    // Segmented column-sum (batch sorted -> few runs per tile -> few atomics)
    int col = t & 127, half = t >> 7;
    int rb = half * 64;
    int re = rb + 64; if (re > valid) re = valid;
    if (rb < re) {
        int cur = sb[rb];
        float acc = 0.f;
        for (int r = rb; r < re; ++r) {
            int g = sb[r];
            if (g != cur) {
                atomicAdd(&g_hsum[(long long)cur * HH + col], acc);
                acc = 0.f; cur = g;
            }
            acc += Os[r * 132 + col];
        }
        atomicAdd(&g_hsum[(long long)cur * HH + col], acc);
    }
}

// out[g,:] = (hsum[g,:]/max(cnt,1)) @ W2 + b2 ; empty graphs -> 0.
__global__ void kernelB(const float* __restrict__ W2, const float* __restrict__ b2,
                        float* __restrict__ out, int G)
{
    __shared__ float sh[64][HH + 1];   // column HH holds the "non-empty" flag
    int g0 = blockIdx.x * 64;
    int t = threadIdx.x;
    for (int idx = t; idx < 64 * HH; idx += 256) {
        int r = idx >> 7, k = idx & 127;
        int g = g0 + r;
        float val = 0.f;
        if (g < G) {
            float cnt = g_counts[g];
            float d = (cnt < 1.f) ? 1.f : cnt;
            val = g_hsum[(long long)g * HH + k] / d;
            if (k == 0) sh[r][HH] = (cnt >= 0.5f) ? 1.f : 0.f;
        } else if (k == 0) sh[r][HH] = 0.f;
        sh[r][k] = val;
    }
    __syncthreads();

    int ccol = t & 127, halfb = t >> 7;
    int rb = halfb * 32;
    float acc[32];
    float bv = b2[ccol];
#pragma unroll
    for (int r = 0; r < 32; r++) acc[r] = bv;
#pragma unroll 8
    for (int k = 0; k < HH; k++) {
        float w = W2[k * O_DIM + ccol];
#pragma unroll
        for (int r = 0; r < 32; r++) acc[r] += sh[rb + r][k] * w;
    }
#pragma unroll
    for (int r = 0; r < 32; r++) {
        int g = g0 + rb + r;
        if (g < G) out[(long long)g * O_DIM + ccol] = acc[r] * sh[rb + r][HH];
    }
}

extern "C" void kernel_launch(void* const* d_in, const int* in_sizes, int n_in,
                              void* d_out, int out_size)
{
    const float* v     = (const float*)d_in[0];
    const int*   batch = (const int*)d_in[1];
    int w = 2;
    if (n_in >= 7 && in_sizes[2] == 1) w = 3;   // skip num_graphs scalar if present
    const float* W1 = (const float*)d_in[w];
    const float* b1 = (const float*)d_in[w + 1];
    const float* W2 = (const float*)d_in[w + 2];
    const float* b2 = (const float*)d_in[w + 3];

    int N = in_sizes[1];
    int G = out_size / O_DIM;
    int hsumN = G * HH;

    int zn = hsumN > G ? hsumN : G;
    zero_kernel<<<(zn + 255) / 256, 256>>>(hsumN, G);

    size_t smem = (size_t)(BK * 132 + BK * HH + BM * 132) * sizeof(float) + BM * sizeof(int);
    cudaFuncSetAttribute((const void*)fused1,
                         cudaFuncAttributeMaxDynamicSharedMemorySize, (int)smem);
    int nb = (N + BM - 1) / BM;
    fused1<<<nb, 256, smem>>>(v, batch, W1, b1, N);

    count_kernel<<<(N + 255) / 256, 256>>>(batch, N);
    kernelB<<<(G + 63) / 64, 256>>>(W2, b2, (float*)d_out, G);
}

// round 5
// speedup vs baseline: 2.3358x; 2.3358x over previous
#include <cuda_runtime.h>
#include <cuda_bf16.h>
#include <cstdint>

#define NEG_SLOPE 0.015f
#define HH    128
#define O_DIM 128

// Scratch: segment sums [G, HH], per-graph counts, pre-split transposed W1.
__device__ float g_hsum[1 << 21];
__device__ float g_counts[1 << 16];
__device__ __nv_bfloat16 g_W1h[128 * 256];   // [n][k], k contiguous
__device__ __nv_bfloat16 g_W1l[128 * 256];

static __device__ __forceinline__ uint32_t smem_u32(const void* p) {
    uint32_t a;
    asm("{ .reg .u64 t; cvta.to.shared.u64 t, %1; cvt.u32.u64 %0, t; }" : "=r"(a) : "l"(p));
    return a;
}
static __device__ __forceinline__ void ldsm4(uint32_t* r, uint32_t addr) {
    asm volatile("ldmatrix.sync.aligned.m8n8.x4.shared.b16 {%0,%1,%2,%3}, [%4];"
                 : "=r"(r[0]), "=r"(r[1]), "=r"(r[2]), "=r"(r[3]) : "r"(addr));
}
static __device__ __forceinline__ void mma16816(float* d, const uint32_t* a,
                                                const uint32_t* b) {
    asm volatile("mma.sync.aligned.m16n8k16.row.col.f32.bf16.bf16.f32 "
                 "{%0,%1,%2,%3}, {%4,%5,%6,%7}, {%8,%9}, {%0,%1,%2,%3};"
                 : "+f"(d[0]), "+f"(d[1]), "+f"(d[2]), "+f"(d[3])
                 : "r"(a[0]), "r"(a[1]), "r"(a[2]), "r"(a[3]), "r"(b[0]), "r"(b[1]));
}

// Zero scratch + pre-split W1 -> bf16 hi/lo, transposed to [n][k].
__global__ void prep_kernel(const float* __restrict__ W1, int hsumN, int G) {
    int i = blockIdx.x * blockDim.x + threadIdx.x;
    if (i < hsumN) g_hsum[i] = 0.f;
    if (i < G)     g_counts[i] = 0.f;
    if (i < 256 * 128) {
        int k = i >> 7, n = i & 127;          // W1 is [256][128] row-major
        float x = W1[i];
        __nv_bfloat16 h = __float2bfloat16(x);
        float lo = x - __bfloat162float(h);
        g_W1h[n * 256 + k] = h;
        g_W1l[n * 256 + k] = __float2bfloat16(lo);
    }
}

// SMEM layout (bytes):
//   [0,512)      sbid[128]
//   [1024,...)   Ah(10240) Al(10240) Bh(10240) Bl(10240)   (stride 40 b16 = 80B/row)
//   [1024,...)   reused as Os[128][130] floats in epilogue
#define AH_OFF 1024
#define AL_OFF (AH_OFF + 10240)
#define BH_OFF (AL_OFF + 10240)
#define BL_OFF (BH_OFF + 10240)
#define SMEM_BYTES (1024 + 128 * 130 * 4)

extern "C" __global__ void __launch_bounds__(256, 2)
fused1(const float* __restrict__ v, const int* __restrict__ batch,
       const float* __restrict__ b1, int N)
{
    extern __shared__ __align__(128) char smem[];
    int*   sbid = (int*)smem;
    float* Os   = (float*)(smem + 1024);
    uint32_t sb = smem_u32(smem);
    const uint32_t Ah_u = sb + AH_OFF, Al_u = sb + AL_OFF;
    const uint32_t Bh_u = sb + BH_OFF, Bl_u = sb + BL_OFF;

    int t = threadIdx.x, lid = t & 31, wid = t >> 5;
    int wm = wid & 3, wn = wid >> 2;          // warp tile: rows wm*32, cols wn*64
    long long r0 = (long long)blockIdx.x * 128;
    int valid = N - (int)r0; if (valid > 128) valid = 128;
    if (t < 128) sbid[t] = (t < valid) ? batch[r0 + t] : -1;

    // Accumulators, bias-initialized. d[mt][nt][0..3]
    float d[2][8][4];
    {
        int cb = wn * 64 + 2 * (lid & 3);
#pragma unroll
        for (int nt = 0; nt < 8; ++nt) {
            float bx = __ldg(b1 + cb + nt * 8);
            float by = __ldg(b1 + cb + nt * 8 + 1);
#pragma unroll
            for (int mt = 0; mt < 2; ++mt) {
                d[mt][nt][0] = bx; d[mt][nt][1] = by;
                d[mt][nt][2] = bx; d[mt][nt][3] = by;
            }
        }
    }

    const float* vb = v + r0 * 256;
    float4 areg[4];

    // Prefetch A chunk 0: 128 rows x 32 k floats; thread -> 4 float4
#pragma unroll
    for (int q = 0; q < 4; ++q) {
        int idx = q * 256 + t, row = idx >> 3, f4 = idx & 7;
        int gr = (row < valid) ? row : (valid - 1);
        areg[q] = *(const float4*)(vb + (long long)gr * 256 + f4 * 4);
    }

    int r8 = lid & 7, grp = lid >> 3;

    for (int c = 0; c < 8; ++c) {
        __syncthreads();   // smem consumed by previous mma phase

        // Store A hi/lo (from prefetched regs)
#pragma unroll
        for (int q = 0; q < 4; ++q) {
            int idx = q * 256 + t, row = idx >> 3, f4 = idx & 7;
            float4 a = areg[q];
            __nv_bfloat162 h01 = make_bfloat162(__float2bfloat16(a.x), __float2bfloat16(a.y));
            __nv_bfloat162 h23 = make_bfloat162(__float2bfloat16(a.z), __float2bfloat16(a.w));
            __nv_bfloat162 l01 = make_bfloat162(
                __float2bfloat16(a.x - __bfloat162float(h01.x)),
                __float2bfloat16(a.y - __bfloat162float(h01.y)));
            __nv_bfloat162 l23 = make_bfloat162(
                __float2bfloat16(a.z - __bfloat162float(h23.x)),
                __float2bfloat16(a.w - __bfloat162float(h23.y)));
            uint32_t off = row * 80 + f4 * 8;
            *(uint2*)(smem + AH_OFF + off) = make_uint2(
                *(uint32_t*)&h01, *(uint32_t*)&h23);
            *(uint2*)(smem + AL_OFF + off) = make_uint2(
                *(uint32_t*)&l01, *(uint32_t*)&l23);
        }
        // B: copy pre-split weights chunk (gmem [n][k] -> smem stride-40)
#pragma unroll
        for (int q = 0; q < 4; ++q) {
            int idx = q * 256 + t;
            int prec = idx >> 9, rem = idx & 511, n = rem >> 2, kq = rem & 3;
            const __nv_bfloat16* src = prec ? g_W1l : g_W1h;
            uint4 w = *(const uint4*)(src + n * 256 + c * 32 + kq * 8);
            *(uint4*)(smem + (prec ? BL_OFF : BH_OFF) + n * 80 + kq * 16) = w;
        }
        __syncthreads();

        // Prefetch next A chunk (overlaps with mma below)
        if (c < 7) {
#pragma unroll
            for (int q = 0; q < 4; ++q) {
                int idx = q * 256 + t, row = idx >> 3, f4 = idx & 7;
                int gr = (row < valid) ? row : (valid - 1);
                areg[q] = *(const float4*)(vb + (long long)gr * 256 + (c + 1) * 32 + f4 * 4);
            }
        }

        // MMA phase: 2 k-steps of 16
#pragma unroll
        for (int kk = 0; kk < 2; ++kk) {
            int k0 = kk * 16;
            int arow = wm * 32 + r8 + (grp & 1) * 8;
            int acol = k0 + (grp >> 1) * 8;
            uint32_t afh[2][4], afl[2][4];
#pragma unroll
            for (int mt = 0; mt < 2; ++mt) {
                uint32_t ao = (arow + mt * 16) * 80 + acol * 2;
                ldsm4(afh[mt], Ah_u + ao);
                ldsm4(afl[mt], Al_u + ao);
            }
#pragma unroll
            for (int ng = 0; ng < 4; ++ng) {
                int nrow = wn * 64 + ng * 16 + r8 + (grp >> 1) * 8;
                int ncol = k0 + (grp & 1) * 8;
                uint32_t bo = nrow * 80 + ncol * 2;
                uint32_t bh[4], bl[4];
                ldsm4(bh, Bh_u + bo);
                ldsm4(bl, Bl_u + bo);
#pragma unroll
                for (int mt = 0; mt < 2; ++mt) {
#pragma unroll
                    for (int sub = 0; sub < 2; ++sub) {
                        float* dd = d[mt][ng * 2 + sub];
                        mma16816(dd, afh[mt], bh + 2 * sub);   // ah*bh
                        mma16816(dd, afl[mt], bh + 2 * sub);   // al*bh
                        mma16816(dd, afh[mt], bl + 2 * sub);   // ah*bl
                    }
                }
            }
        }
    }
    __syncthreads();   // operand smem free -> reuse as Os

    // Epilogue: LeakyReLU, stage tile (stride 130 floats)
#pragma unroll
    for (int mt = 0; mt < 2; ++mt) {
        int rA = wm * 32 + mt * 16 + (lid >> 2);
#pragma unroll
        for (int nt = 0; nt < 8; ++nt) {
            int cc = wn * 64 + nt * 8 + 2 * (lid & 3);
            float x0 = d[mt][nt][0], x1 = d[mt][nt][1];
            float x2 = d[mt][nt][2], x3 = d[mt][nt][3];
            x0 = (x0 >= 0.f) ? x0 : NEG_SLOPE * x0;
            x1 = (x1 >= 0.f) ? x1 : NEG_SLOPE * x1;
            x2 = (x2 >= 0.f) ? x2 : NEG_SLOPE * x2;
            x3 = (x3 >= 0.f) ? x3 : NEG_SLOPE * x3;
            *(float2*)(Os + rA * 130 + cc)       = make_float2(x0, x1);
            *(float2*)(Os + (rA + 8) * 130 + cc) = make_float2(x2, x3);
        }
    }
    __syncthreads();

    // Segmented column-sum + counts (batch sorted -> few runs per tile)
    {
        int col = t & 127, half = t >> 7;
        int rb = half * 64;
        int re = rb + 64; if (re > valid) re = valid;
        if (rb < re) {
            int cur = sbid[rb];
            float acc = 0.f; int cnt = 0;
            for (int r = rb; r < re; ++r) {
                int g = sbid[r];
                if (g != cur) {
                    atomicAdd(&g_hsum[(long long)cur * HH + col], acc);
                    if (col == 0) atomicAdd(&g_counts[cur], (float)cnt);
                    acc = 0.f; cnt = 0; cur = g;
                }
                acc += Os[r * 130 + col];
                cnt++;
            }
            atomicAdd(&g_hsum[(long long)cur * HH + col], acc);
            if (col == 0) atomicAdd(&g_counts[cur], (float)cnt);
        }
    }
}

// out[g,:] = (hsum[g,:]/max(cnt,1)) @ W2 + b2 ; empty graphs -> 0. 16 graphs/block.
__global__ void __launch_bounds__(256)
kernelB(const float* __restrict__ W2, const float* __restrict__ b2,
        float* __restrict__ out, int G)
{
    __shared__ float sh[16][130];   // col 128 = non-empty flag
    int g0 = blockIdx.x * 16;
    int t = threadIdx.x;
    for (int idx = t; idx < 16 * 128; idx += 256) {
        int r = idx >> 7, k = idx & 127;
        int g = g0 + r;
        float val = 0.f, flag = 0.f;
        if (g < G) {
            float cnt = g_counts[g];
            float dn = (cnt < 1.f) ? 1.f : cnt;
            val = g_hsum[(long long)g * HH + k] / dn;
            flag = (cnt >= 0.5f) ? 1.f : 0.f;
        }
        sh[r][k] = val;
        if (k == 0) sh[r][128] = flag;
    }
    __syncthreads();

    int col = t & 127, rg = t >> 7;
    float bv = b2[col];
    float acc[8];
#pragma unroll
    for (int r = 0; r < 8; ++r) acc[r] = bv;
#pragma unroll 4
    for (int k = 0; k < 128; ++k) {
        float w = W2[k * O_DIM + col];
#pragma unroll
        for (int r = 0; r < 8; ++r) acc[r] += sh[rg * 8 + r][k] * w;
    }
#pragma unroll
    for (int r = 0; r < 8; ++r) {
        int g = g0 + rg * 8 + r;
        if (g < G) out[(long long)g * O_DIM + col] = acc[r] * sh[rg * 8 + r][128];
    }
}

extern "C" void kernel_launch(void* const* d_in, const int* in_sizes, int n_in,
                              void* d_out, int out_size)
{
    const float* v     = (const float*)d_in[0];
    const int*   batch = (const int*)d_in[1];
    int w = 2;
    if (n_in >= 7 && in_sizes[2] == 1) w = 3;   // skip num_graphs scalar if present
    const float* W1 = (const float*)d_in[w];
    const float* b1 = (const float*)d_in[w + 1];
    const float* W2 = (const float*)d_in[w + 2];
    const float* b2 = (const float*)d_in[w + 3];

    int N = in_sizes[1];
    int G = out_size / O_DIM;
    int hsumN = G * HH;

    int zn = hsumN; if (zn < G) zn = G; if (zn < 256 * 128) zn = 256 * 128;
    prep_kernel<<<(zn + 255) / 256, 256>>>(W1, hsumN, G);

    static int smem_set = 0;
    if (!smem_set) {
        cudaFuncSetAttribute((const void*)fused1,
                             cudaFuncAttributeMaxDynamicSharedMemorySize, SMEM_BYTES);
        smem_set = 1;
    }
    int nb = (N + 127) / 128;
    fused1<<<nb, 256, SMEM_BYTES>>>(v, batch, b1, N);

    kernelB<<<(G + 15) / 16, 256>>>(W2, b2, (float*)d_out, G);
}

// round 6
// speedup vs baseline: 2.5717x; 1.1010x over previous
#include <cuda_runtime.h>
#include <cuda_bf16.h>
#include <cstdint>

#define NEG_SLOPE 0.015f
#define HH    128
#define O_DIM 128

// Scratch: segment sums [G, HH], per-graph counts, pre-split transposed W1.
__device__ float g_hsum[1 << 21];
__device__ float g_counts[1 << 16];
__device__ __nv_bfloat16 g_W1h[128 * 256];   // [n][k], k contiguous
__device__ __nv_bfloat16 g_W1l[128 * 256];

static __device__ __forceinline__ uint32_t smem_u32(const void* p) {
    uint32_t a;
    asm("{ .reg .u64 t; cvta.to.shared.u64 t, %1; cvt.u32.u64 %0, t; }" : "=r"(a) : "l"(p));
    return a;
}
static __device__ __forceinline__ void ldsm4(uint32_t* r, uint32_t addr) {
    asm volatile("ldmatrix.sync.aligned.m8n8.x4.shared.b16 {%0,%1,%2,%3}, [%4];"
                 : "=r"(r[0]), "=r"(r[1]), "=r"(r[2]), "=r"(r[3]) : "r"(addr));
}
static __device__ __forceinline__ void mma16816(float* d, const uint32_t* a,
                                                const uint32_t* b) {
    asm volatile("mma.sync.aligned.m16n8k16.row.col.f32.bf16.bf16.f32 "
                 "{%0,%1,%2,%3}, {%4,%5,%6,%7}, {%8,%9}, {%0,%1,%2,%3};"
                 : "+f"(d[0]), "+f"(d[1]), "+f"(d[2]), "+f"(d[3])
                 : "r"(a[0]), "r"(a[1]), "r"(a[2]), "r"(a[3]), "r"(b[0]), "r"(b[1]));
}
static __device__ __forceinline__ void cp16(uint32_t dst, const void* src) {
    asm volatile("cp.async.cg.shared.global [%0], [%1], 16;" :: "r"(dst), "l"(src));
}

// Zero scratch + pre-split W1 -> bf16 hi/lo, transposed to [n][k].
__global__ void prep_kernel(const float* __restrict__ W1, int hsumN, int G) {
    int i = blockIdx.x * blockDim.x + threadIdx.x;
    if (i < hsumN) g_hsum[i] = 0.f;
    if (i < G)     g_counts[i] = 0.f;
    if (i < 256 * 128) {
        int k = i >> 7, n = i & 127;          // W1 is [256][128] row-major
        float x = W1[i];
        __nv_bfloat16 h = __float2bfloat16(x);
        float lo = x - __bfloat162float(h);
        g_W1h[n * 256 + k] = h;
        g_W1l[n * 256 + k] = __float2bfloat16(lo);
    }
}

// SMEM (bytes):
//  [0,512)    sbid[128]
//  [1024,..)  2 stages x {Ah,Al,Bh,Bl}, each 10240B (stride 40 b16 = 80B/row)
//  [1024,..)  reused as Os[128][130] floats in the epilogue
#define ST_SZ   40960
#define A_H     0
#define A_L     10240
#define B_H     20480
#define B_L     30720
#define SMEM_BYTES (1024 + 2 * ST_SZ)

extern "C" __global__ void __launch_bounds__(256, 2)
fused1(const float* __restrict__ v, const int* __restrict__ batch,
       const float* __restrict__ b1, int N)
{
    extern __shared__ __align__(128) char smem[];
    int*   sbid = (int*)smem;
    float* Os   = (float*)(smem + 1024);
    uint32_t sb = smem_u32(smem);

    int t = threadIdx.x, lid = t & 31, wid = t >> 5;
    int wm = wid & 3, wn = wid >> 2;          // warp tile: rows wm*32, cols wn*64
    long long r0 = (long long)blockIdx.x * 128;
    int valid = N - (int)r0; if (valid > 128) valid = 128;
    if (t < 128) sbid[t] = (t < valid) ? batch[r0 + t] : -1;

    // Accumulators, bias-initialized. d[mt][nt][0..3]
    float d[2][8][4];
    {
        int cb = wn * 64 + 2 * (lid & 3);
#pragma unroll
        for (int nt = 0; nt < 8; ++nt) {
            float bx = __ldg(b1 + cb + nt * 8);
            float by = __ldg(b1 + cb + nt * 8 + 1);
#pragma unroll
            for (int mt = 0; mt < 2; ++mt) {
                d[mt][nt][0] = bx; d[mt][nt][1] = by;
                d[mt][nt][2] = bx; d[mt][nt][3] = by;
            }
        }
    }

    const float* vb = v + r0 * 256;
    int arow_ld = t >> 1, af4 = (t & 1) * 4;           // (unused helper removed)
    (void)arow_ld; (void)af4;

    float4 areg[4];
    int r8 = lid & 7, grp = lid >> 3;

    // ---- helpers as lambdas ----
    auto lda = [&](int c) {
#pragma unroll
        for (int q = 0; q < 4; ++q) {
            int idx = q * 256 + t, row = idx >> 3, f4 = idx & 7;
            int gr = (row < valid) ? row : (valid - 1);
            areg[q] = *(const float4*)(vb + (long long)gr * 256 + c * 32 + f4 * 4);
        }
    };
    auto sta = [&](int s) {   // convert+store A from areg into stage s
        char* base = smem + 1024 + s * ST_SZ;
#pragma unroll
        for (int q = 0; q < 4; ++q) {
            int idx = q * 256 + t, row = idx >> 3, f4 = idx & 7;
            float4 a = areg[q];
            __nv_bfloat162 h01 = __floats2bfloat162_rn(a.x, a.y);
            __nv_bfloat162 h23 = __floats2bfloat162_rn(a.z, a.w);
            __nv_bfloat162 l01 = __floats2bfloat162_rn(
                a.x - __bfloat162float(h01.x), a.y - __bfloat162float(h01.y));
            __nv_bfloat162 l23 = __floats2bfloat162_rn(
                a.z - __bfloat162float(h23.x), a.w - __bfloat162float(h23.y));
            uint32_t off = row * 80 + f4 * 8;
            *(uint2*)(base + A_H + off) = make_uint2(*(uint32_t*)&h01, *(uint32_t*)&h23);
            *(uint2*)(base + A_L + off) = make_uint2(*(uint32_t*)&l01, *(uint32_t*)&l23);
        }
    };
    auto ldb = [&](int c, int s) {   // cp.async B chunk c into stage s
        uint32_t base = sb + 1024 + s * ST_SZ;
#pragma unroll
        for (int q = 0; q < 2; ++q) {
            int idx = q * 256 + t;              // 0..511
            int n = idx >> 2, kq = idx & 3;
            uint32_t doff = n * 80 + kq * 16;
            const __nv_bfloat16* sh_ = g_W1h + n * 256 + c * 32 + kq * 8;
            const __nv_bfloat16* sl_ = g_W1l + n * 256 + c * 32 + kq * 8;
            cp16(base + B_H + doff, sh_);
            cp16(base + B_L + doff, sl_);
        }
        asm volatile("cp.async.commit_group;" ::: "memory");
    };

    // ---- prologue: fill stage 0 with chunk 0 ----
    lda(0);
    sta(0);
    ldb(0, 0);
    lda(1);
    asm volatile("cp.async.wait_group 0;" ::: "memory");
    __syncthreads();

    for (int c = 0; c < 8; ++c) {
        int s = c & 1;
        // issue next-stage fill first (overlaps with MMA below)
        if (c < 7) { sta(s ^ 1); ldb(c + 1, s ^ 1); }

        // MMA phase on stage s
        uint32_t ab = sb + 1024 + s * ST_SZ;
#pragma unroll
        for (int kk = 0; kk < 2; ++kk) {
            int k0 = kk * 16;
            int arow = wm * 32 + r8 + (grp & 1) * 8;
            int acol = k0 + (grp >> 1) * 8;
            uint32_t afh[2][4], afl[2][4];
#pragma unroll
            for (int mt = 0; mt < 2; ++mt) {
                uint32_t ao = (arow + mt * 16) * 80 + acol * 2;
                ldsm4(afh[mt], ab + A_H + ao);
                ldsm4(afl[mt], ab + A_L + ao);
            }
#pragma unroll
            for (int ng = 0; ng < 4; ++ng) {
                int nrow = wn * 64 + ng * 16 + r8 + (grp >> 1) * 8;
                int ncol = k0 + (grp & 1) * 8;
                uint32_t bo = nrow * 80 + ncol * 2;
                uint32_t bh[4], bl[4];
                ldsm4(bh, ab + B_H + bo);
                ldsm4(bl, ab + B_L + bo);
#pragma unroll
                for (int mt = 0; mt < 2; ++mt) {
#pragma unroll
                    for (int sub = 0; sub < 2; ++sub) {
                        float* dd = d[mt][ng * 2 + sub];
                        mma16816(dd, afh[mt], bh + 2 * sub);   // ah*bh
                        mma16816(dd, afl[mt], bh + 2 * sub);   // al*bh
                        mma16816(dd, afh[mt], bl + 2 * sub);   // ah*bl
                    }
                }
            }
        }

        if (c < 6) lda(c + 2);
        if (c < 7) asm volatile("cp.async.wait_group 0;" ::: "memory");
        __syncthreads();
    }

    // Epilogue: LeakyReLU, stage tile (stride 130 floats)
#pragma unroll
    for (int mt = 0; mt < 2; ++mt) {
        int rA = wm * 32 + mt * 16 + (lid >> 2);
#pragma unroll
        for (int nt = 0; nt < 8; ++nt) {
            int cc = wn * 64 + nt * 8 + 2 * (lid & 3);
            float x0 = d[mt][nt][0], x1 = d[mt][nt][1];
            float x2 = d[mt][nt][2], x3 = d[mt][nt][3];
            x0 = (x0 >= 0.f) ? x0 : NEG_SLOPE * x0;
            x1 = (x1 >= 0.f) ? x1 : NEG_SLOPE * x1;
            x2 = (x2 >= 0.f) ? x2 : NEG_SLOPE * x2;
            x3 = (x3 >= 0.f) ? x3 : NEG_SLOPE * x3;
            *(float2*)(Os + rA * 130 + cc)       = make_float2(x0, x1);
            *(float2*)(Os + (rA + 8) * 130 + cc) = make_float2(x2, x3);
        }
    }
    __syncthreads();

    // Segmented column-sum + counts (batch sorted -> few runs per tile)
    {
        int col = t & 127, half = t >> 7;
        int rb = half * 64;
        int re = rb + 64; if (re > valid) re = valid;
        if (rb < re) {
            int cur = sbid[rb];
            float acc = 0.f; int cnt = 0;
            for (int r = rb; r < re; ++r) {
                int g = sbid[r];
                if (g != cur) {
                    atomicAdd(&g_hsum[(long long)cur * HH + col], acc);
                    if (col == 0) atomicAdd(&g_counts[cur], (float)cnt);
                    acc = 0.f; cnt = 0; cur = g;
                }
                acc += Os[r * 130 + col];
                cnt++;
            }
            atomicAdd(&g_hsum[(long long)cur * HH + col], acc);
            if (col == 0) atomicAdd(&g_counts[cur], (float)cnt);
        }
    }
}

// out[g,:] = (hsum[g,:]/max(cnt,1)) @ W2 + b2 ; empty graphs -> 0. 16 graphs/block.
__global__ void __launch_bounds__(256)
kernelB(const float* __restrict__ W2, const float* __restrict__ b2,
        float* __restrict__ out, int G)
{
    __shared__ float sh[16][130];   // col 128 = non-empty flag
    int g0 = blockIdx.x * 16;
    int t = threadIdx.x;
    for (int idx = t; idx < 16 * 128; idx += 256) {
        int r = idx >> 7, k = idx & 127;
        int g = g0 + r;
        float val = 0.f, flag = 0.f;
        if (g < G) {
            float cnt = g_counts[g];
            float dn = (cnt < 1.f) ? 1.f : cnt;
            val = g_hsum[(long long)g * HH + k] / dn;
            flag = (cnt >= 0.5f) ? 1.f : 0.f;
        }
        sh[r][k] = val;
        if (k == 0) sh[r][128] = flag;
    }
    __syncthreads();

    int col = t & 127, rg = t >> 7;
    float bv = b2[col];
    float acc[8];
#pragma unroll
    for (int r = 0; r < 8; ++r) acc[r] = bv;
#pragma unroll 4
    for (int k = 0; k < 128; ++k) {
        float w = W2[k * O_DIM + col];
#pragma unroll
        for (int r = 0; r < 8; ++r) acc[r] += sh[rg * 8 + r][k] * w;
    }
#pragma unroll
    for (int r = 0; r < 8; ++r) {
        int g = g0 + rg * 8 + r;
        if (g < G) out[(long long)g * O_DIM + col] = acc[r] * sh[rg * 8 + r][128];
    }
}

extern "C" void kernel_launch(void* const* d_in, const int* in_sizes, int n_in,
                              void* d_out, int out_size)
{
    const float* v     = (const float*)d_in[0];
    const int*   batch = (const int*)d_in[1];
    int w = 2;
    if (n_in >= 7 && in_sizes[2] == 1) w = 3;   // skip num_graphs scalar if present
    const float* W1 = (const float*)d_in[w];
    const float* b1 = (const float*)d_in[w + 1];
    const float* W2 = (const float*)d_in[w + 2];
    const float* b2 = (const float*)d_in[w + 3];

    int N = in_sizes[1];
    int G = out_size / O_DIM;
    int hsumN = G * HH;

    int zn = hsumN; if (zn < G) zn = G; if (zn < 256 * 128) zn = 256 * 128;
    prep_kernel<<<(zn + 255) / 256, 256>>>(W1, hsumN, G);

    static int smem_set = 0;
    if (!smem_set) {
        cudaFuncSetAttribute((const void*)fused1,
                             cudaFuncAttributeMaxDynamicSharedMemorySize, SMEM_BYTES);
        smem_set = 1;
    }
    int nb = (N + 127) / 128;
    fused1<<<nb, 256, SMEM_BYTES>>>(v, batch, b1, N);

    kernelB<<<(G + 15) / 16, 256>>>(W2, b2, (float*)d_out, G);
}

// round 7
// speedup vs baseline: 3.0008x; 1.1669x over previous
#include <cuda_runtime.h>
#include <cuda_fp16.h>
#include <cstdint>

#define NEG_SLOPE 0.015f
#define HH    128
#define O_DIM 128

// Scratch: segment sums [G, HH], per-graph counts, fp16 transposed W1.
__device__ float g_hsum[1 << 21];
__device__ float g_counts[1 << 16];
__device__ __half g_W1h[128 * 256];   // [n][k], k contiguous

static __device__ __forceinline__ uint32_t smem_u32(const void* p) {
    uint32_t a;
    asm("{ .reg .u64 t; cvta.to.shared.u64 t, %1; cvt.u32.u64 %0, t; }" : "=r"(a) : "l"(p));
    return a;
}
static __device__ __forceinline__ void ldsm4(uint32_t* r, uint32_t addr) {
    asm volatile("ldmatrix.sync.aligned.m8n8.x4.shared.b16 {%0,%1,%2,%3}, [%4];"
                 : "=r"(r[0]), "=r"(r[1]), "=r"(r[2]), "=r"(r[3]) : "r"(addr));
}
static __device__ __forceinline__ void mma16816(float* d, const uint32_t* a,
                                                const uint32_t* b) {
    asm volatile("mma.sync.aligned.m16n8k16.row.col.f32.f16.f16.f32 "
                 "{%0,%1,%2,%3}, {%4,%5,%6,%7}, {%8,%9}, {%0,%1,%2,%3};"
                 : "+f"(d[0]), "+f"(d[1]), "+f"(d[2]), "+f"(d[3])
                 : "r"(a[0]), "r"(a[1]), "r"(a[2]), "r"(a[3]), "r"(b[0]), "r"(b[1]));
}
static __device__ __forceinline__ void cp16(uint32_t dst, const void* src) {
    asm volatile("cp.async.cg.shared.global [%0], [%1], 16;" :: "r"(dst), "l"(src));
}

// Zero scratch + W1 -> fp16, transposed to [n][k].
__global__ void prep_kernel(const float* __restrict__ W1, int hsumN, int G) {
    int i = blockIdx.x * blockDim.x + threadIdx.x;
    if (i < hsumN) g_hsum[i] = 0.f;
    if (i < G)     g_counts[i] = 0.f;
    if (i < 256 * 128) {
        int k = i >> 7, n = i & 127;          // W1 is [256][128] row-major
        g_W1h[n * 256 + k] = __float2half_rn(W1[i]);
    }
}

// SMEM (bytes):
//  [0,512)    sbid[128]
//  [1024,..)  2 stages x {Ah,Al,Bh}, each 10240B (stride 40 h16 = 80B/row)
//  [1024,..)  reused as Os[128][130] floats in the epilogue
#define ST_SZ   30720
#define A_H     0
#define A_L     10240
#define B_H     20480
#define SMEM_BYTES (1024 + 128 * 130 * 4)

extern "C" __global__ void __launch_bounds__(256, 2)
fused1(const float* __restrict__ v, const int* __restrict__ batch,
       const float* __restrict__ b1, int N)
{
    extern __shared__ __align__(128) char smem[];
    int*   sbid = (int*)smem;
    float* Os   = (float*)(smem + 1024);
    uint32_t sb = smem_u32(smem);

    int t = threadIdx.x, lid = t & 31, wid = t >> 5;
    int wm = wid & 3, wn = wid >> 2;          // warp tile: rows wm*32, cols wn*64
    long long r0 = (long long)blockIdx.x * 128;
    int valid = N - (int)r0; if (valid > 128) valid = 128;
    if (t < 128) sbid[t] = (t < valid) ? batch[r0 + t] : -1;

    // Accumulators, bias-initialized. d[mt][nt][0..3]
    float d[2][8][4];
    {
        int cb = wn * 64 + 2 * (lid & 3);
#pragma unroll
        for (int nt = 0; nt < 8; ++nt) {
            float bx = __ldg(b1 + cb + nt * 8);
            float by = __ldg(b1 + cb + nt * 8 + 1);
#pragma unroll
            for (int mt = 0; mt < 2; ++mt) {
                d[mt][nt][0] = bx; d[mt][nt][1] = by;
                d[mt][nt][2] = bx; d[mt][nt][3] = by;
            }
        }
    }

    const float* vb = v + r0 * 256;
    float4 areg[4];
    int r8 = lid & 7, grp = lid >> 3;

    auto lda = [&](int c) {
#pragma unroll
        for (int q = 0; q < 4; ++q) {
            int idx = q * 256 + t, row = idx >> 3, f4 = idx & 7;
            int gr = (row < valid) ? row : (valid - 1);
            areg[q] = *(const float4*)(vb + (long long)gr * 256 + c * 32 + f4 * 4);
        }
    };
    auto sta = [&](int s) {   // convert+store A hi/lo (fp16) into stage s
        char* base = smem + 1024 + s * ST_SZ;
#pragma unroll
        for (int q = 0; q < 4; ++q) {
            int idx = q * 256 + t, row = idx >> 3, f4 = idx & 7;
            float4 a = areg[q];
            __half hx = __float2half_rn(a.x), hy = __float2half_rn(a.y);
            __half hz = __float2half_rn(a.z), hw = __float2half_rn(a.w);
            __half2 h01 = __halves2half2(hx, hy);
            __half2 h23 = __halves2half2(hz, hw);
            __half2 l01 = __halves2half2(__float2half_rn(a.x - __half2float(hx)),
                                         __float2half_rn(a.y - __half2float(hy)));
            __half2 l23 = __halves2half2(__float2half_rn(a.z - __half2float(hz)),
                                         __float2half_rn(a.w - __half2float(hw)));
            uint32_t off = row * 80 + f4 * 8;
            *(uint2*)(base + A_H + off) = make_uint2(*(uint32_t*)&h01, *(uint32_t*)&h23);
            *(uint2*)(base + A_L + off) = make_uint2(*(uint32_t*)&l01, *(uint32_t*)&l23);
        }
    };
    auto ldb = [&](int c, int s) {   // cp.async B chunk c (fp16 hi only)
        uint32_t base = sb + 1024 + s * ST_SZ;
#pragma unroll
        for (int q = 0; q < 2; ++q) {
            int idx = q * 256 + t;              // 0..511
            int n = idx >> 2, kq = idx & 3;
            cp16(base + B_H + n * 80 + kq * 16, g_W1h + n * 256 + c * 32 + kq * 8);
        }
        asm volatile("cp.async.commit_group;" ::: "memory");
    };

    // ---- prologue ----
    lda(0);
    sta(0);
    ldb(0, 0);
    lda(1);
    asm volatile("cp.async.wait_group 0;" ::: "memory");
    __syncthreads();

    for (int c = 0; c < 8; ++c) {
        int s = c & 1;
        if (c < 7) { sta(s ^ 1); ldb(c + 1, s ^ 1); }

        uint32_t ab = sb + 1024 + s * ST_SZ;
#pragma unroll
        for (int kk = 0; kk < 2; ++kk) {
            int k0 = kk * 16;
            int arow = wm * 32 + r8 + (grp & 1) * 8;
            int acol = k0 + (grp >> 1) * 8;
            uint32_t afh[2][4], afl[2][4];
#pragma unroll
            for (int mt = 0; mt < 2; ++mt) {
                uint32_t ao = (arow + mt * 16) * 80 + acol * 2;
                ldsm4(afh[mt], ab + A_H + ao);
                ldsm4(afl[mt], ab + A_L + ao);
            }
#pragma unroll
            for (int ng = 0; ng < 4; ++ng) {
                int nrow = wn * 64 + ng * 16 + r8 + (grp >> 1) * 8;
                int ncol = k0 + (grp & 1) * 8;
                uint32_t bh[4];
                ldsm4(bh, ab + B_H + nrow * 80 + ncol * 2);
#pragma unroll
                for (int mt = 0; mt < 2; ++mt) {
#pragma unroll
                    for (int sub = 0; sub < 2; ++sub) {
                        float* dd = d[mt][ng * 2 + sub];
                        mma16816(dd, afh[mt], bh + 2 * sub);   // ah*bh
                        mma16816(dd, afl[mt], bh + 2 * sub);   // al*bh
                    }
                }
            }
        }

        if (c < 6) lda(c + 2);
        if (c < 7) asm volatile("cp.async.wait_group 0;" ::: "memory");
        __syncthreads();
    }

    // Epilogue: LeakyReLU, stage tile (stride 130 floats)
#pragma unroll
    for (int mt = 0; mt < 2; ++mt) {
        int rA = wm * 32 + mt * 16 + (lid >> 2);
#pragma unroll
        for (int nt = 0; nt < 8; ++nt) {
            int cc = wn * 64 + nt * 8 + 2 * (lid & 3);
            float x0 = d[mt][nt][0], x1 = d[mt][nt][1];
            float x2 = d[mt][nt][2], x3 = d[mt][nt][3];
            x0 = (x0 >= 0.f) ? x0 : NEG_SLOPE * x0;
            x1 = (x1 >= 0.f) ? x1 : NEG_SLOPE * x1;
            x2 = (x2 >= 0.f) ? x2 : NEG_SLOPE * x2;
            x3 = (x3 >= 0.f) ? x3 : NEG_SLOPE * x3;
            *(float2*)(Os + rA * 130 + cc)       = make_float2(x0, x1);
            *(float2*)(Os + (rA + 8) * 130 + cc) = make_float2(x2, x3);
        }
    }
    __syncthreads();

    // Segmented column-sum + counts (batch sorted -> few runs per tile)
    {
        int col = t & 127, half = t >> 7;
        int rb = half * 64;
        int re = rb + 64; if (re > valid) re = valid;
        if (rb < re) {
            int cur = sbid[rb];
            float acc = 0.f; int cnt = 0;
            for (int r = rb; r < re; ++r) {
                int g = sbid[r];
                if (g != cur) {
                    atomicAdd(&g_hsum[(long long)cur * HH + col], acc);
                    if (col == 0) atomicAdd(&g_counts[cur], (float)cnt);
                    acc = 0.f; cnt = 0; cur = g;
                }
                acc += Os[r * 130 + col];
                cnt++;
            }
            atomicAdd(&g_hsum[(long long)cur * HH + col], acc);
            if (col == 0) atomicAdd(&g_counts[cur], (float)cnt);
        }
    }
}

// out[g,:] = (hsum[g,:]/max(cnt,1)) @ W2 + b2 ; empty graphs -> 0. 16 graphs/block.
__global__ void __launch_bounds__(256)
kernelB(const float* __restrict__ W2, const float* __restrict__ b2,
        float* __restrict__ out, int G)
{
    __shared__ float sh[16][130];   // col 128 = non-empty flag
    int g0 = blockIdx.x * 16;
    int t = threadIdx.x;
    for (int idx = t; idx < 16 * 128; idx += 256) {
        int r = idx >> 7, k = idx & 127;
        int g = g0 + r;
        float val = 0.f, flag = 0.f;
        if (g < G) {
            float cnt = g_counts[g];
            float dn = (cnt < 1.f) ? 1.f : cnt;
            val = g_hsum[(long long)g * HH + k] / dn;
            flag = (cnt >= 0.5f) ? 1.f : 0.f;
        }
        sh[r][k] = val;
        if (k == 0) sh[r][128] = flag;
    }
    __syncthreads();

    int col = t & 127, rg = t >> 7;
    float bv = b2[col];
    float acc[8];
#pragma unroll
    for (int r = 0; r < 8; ++r) acc[r] = bv;
#pragma unroll 4
    for (int k = 0; k < 128; ++k) {
        float w = W2[k * O_DIM + col];
#pragma unroll
        for (int r = 0; r < 8; ++r) acc[r] += sh[rg * 8 + r][k] * w;
    }
#pragma unroll
    for (int r = 0; r < 8; ++r) {
        int g = g0 + rg * 8 + r;
        if (g < G) out[(long long)g * O_DIM + col] = acc[r] * sh[rg * 8 + r][128];
    }
}

extern "C" void kernel_launch(void* const* d_in, const int* in_sizes, int n_in,
                              void* d_out, int out_size)
{
    const float* v     = (const float*)d_in[0];
    const int*   batch = (const int*)d_in[1];
    int w = 2;
    if (n_in >= 7 && in_sizes[2] == 1) w = 3;   // skip num_graphs scalar if present
    const float* W1 = (const float*)d_in[w];
    const float* b1 = (const float*)d_in[w + 1];
    const float* W2 = (const float*)d_in[w + 2];
    const float* b2 = (const float*)d_in[w + 3];

    int N = in_sizes[1];
    int G = out_size / O_DIM;
    int hsumN = G * HH;

    int zn = hsumN; if (zn < G) zn = G; if (zn < 256 * 128) zn = 256 * 128;
    prep_kernel<<<(zn + 255) / 256, 256>>>(W1, hsumN, G);

    static int smem_set = 0;
    if (!smem_set) {
        cudaFuncSetAttribute((const void*)fused1,
                             cudaFuncAttributeMaxDynamicSharedMemorySize, SMEM_BYTES);
        smem_set = 1;
    }
    int nb = (N + 127) / 128;
    fused1<<<nb, 256, SMEM_BYTES>>>(v, batch, b1, N);

    kernelB<<<(G + 15) / 16, 256>>>(W2, b2, (float*)d_out, G);
}

// round 8
// speedup vs baseline: 3.8169x; 1.2720x over previous
#include <cuda_runtime.h>
#include <cuda_fp16.h>
#include <cstdint>

#define NEG_SLOPE 0.015f
#define HH    128
#define O_DIM 128

// Scratch: segment sums [G, HH], per-graph counts, fp16 transposed W1.
__device__ float g_hsum[1 << 21];
__device__ float g_counts[1 << 16];
__device__ __half g_W1h[128 * 256];   // [n][k], k contiguous

static __device__ __forceinline__ uint32_t smem_u32(const void* p) {
    uint32_t a;
    asm("{ .reg .u64 t; cvta.to.shared.u64 t, %1; cvt.u32.u64 %0, t; }" : "=r"(a) : "l"(p));
    return a;
}
static __device__ __forceinline__ void ldsm4(uint32_t* r, uint32_t addr) {
    asm volatile("ldmatrix.sync.aligned.m8n8.x4.shared.b16 {%0,%1,%2,%3}, [%4];"
                 : "=r"(r[0]), "=r"(r[1]), "=r"(r[2]), "=r"(r[3]) : "r"(addr));
}
static __device__ __forceinline__ void mma16816(float* d, const uint32_t* a,
                                                const uint32_t* b) {
    asm volatile("mma.sync.aligned.m16n8k16.row.col.f32.f16.f16.f32 "
                 "{%0,%1,%2,%3}, {%4,%5,%6,%7}, {%8,%9}, {%0,%1,%2,%3};"
                 : "+f"(d[0]), "+f"(d[1]), "+f"(d[2]), "+f"(d[3])
                 : "r"(a[0]), "r"(a[1]), "r"(a[2]), "r"(a[3]), "r"(b[0]), "r"(b[1]));
}
static __device__ __forceinline__ void cp16(uint32_t dst, const void* src) {
    asm volatile("cp.async.cg.shared.global [%0], [%1], 16;" :: "r"(dst), "l"(src));
}

// Zero scratch + W1 -> fp16, transposed to [n][k].
__global__ void prep_kernel(const float* __restrict__ W1, int hsumN, int G) {
    int i = blockIdx.x * blockDim.x + threadIdx.x;
    if (i < hsumN) g_hsum[i] = 0.f;
    if (i < G)     g_counts[i] = 0.f;
    if (i < 256 * 128) {
        int k = i >> 7, n = i & 127;          // W1 is [256][128] row-major
        g_W1h[n * 256 + k] = __float2half_rn(W1[i]);
    }
}

// SMEM (bytes):
//  [0,512)    sbid[128]
//  [1024,..)  2 stages x {Ah,Bh}, each 10240B (stride 40 h16 = 80B/row)
//  [1024,..)  reused as Os[128][130] floats in the epilogue
#define ST_SZ   20480
#define A_H     0
#define B_H     10240
#define SMEM_BYTES (1024 + 128 * 130 * 4)

extern "C" __global__ void __launch_bounds__(256, 2)
fused1(const float* __restrict__ v, const int* __restrict__ batch,
       const float* __restrict__ b1, int N)
{
    extern __shared__ __align__(128) char smem[];
    int*   sbid = (int*)smem;
    float* Os   = (float*)(smem + 1024);
    uint32_t sb = smem_u32(smem);

    int t = threadIdx.x, lid = t & 31, wid = t >> 5;
    int wm = wid & 3, wn = wid >> 2;          // warp tile: rows wm*32, cols wn*64
    long long r0 = (long long)blockIdx.x * 128;
    int valid = N - (int)r0; if (valid > 128) valid = 128;
    if (t < 128) sbid[t] = (t < valid) ? batch[r0 + t] : -1;

    // Accumulators, bias-initialized. d[mt][nt][0..3]
    float d[2][8][4];
    {
        int cb = wn * 64 + 2 * (lid & 3);
#pragma unroll
        for (int nt = 0; nt < 8; ++nt) {
            float bx = __ldg(b1 + cb + nt * 8);
            float by = __ldg(b1 + cb + nt * 8 + 1);
#pragma unroll
            for (int mt = 0; mt < 2; ++mt) {
                d[mt][nt][0] = bx; d[mt][nt][1] = by;
                d[mt][nt][2] = bx; d[mt][nt][3] = by;
            }
        }
    }

    const float* vb = v + r0 * 256;
    float4 areg[4];
    int r8 = lid & 7, grp = lid >> 3;

    auto lda = [&](int c) {
#pragma unroll
        for (int q = 0; q < 4; ++q) {
            int idx = q * 256 + t, row = idx >> 3, f4 = idx & 7;
            int gr = (row < valid) ? row : (valid - 1);
            areg[q] = *(const float4*)(vb + (long long)gr * 256 + c * 32 + f4 * 4);
        }
    };
    auto sta = [&](int s) {   // convert+store A (fp16) into stage s
        char* base = smem + 1024 + s * ST_SZ;
#pragma unroll
        for (int q = 0; q < 4; ++q) {
            int idx = q * 256 + t, row = idx >> 3, f4 = idx & 7;
            float4 a = areg[q];
            __half2 h01 = __floats2half2_rn(a.x, a.y);
            __half2 h23 = __floats2half2_rn(a.z, a.w);
            *(uint2*)(base + A_H + row * 80 + f4 * 8) =
                make_uint2(*(uint32_t*)&h01, *(uint32_t*)&h23);
        }
    };
    auto ldb = [&](int c, int s) {   // cp.async B chunk c (fp16)
        uint32_t base = sb + 1024 + s * ST_SZ;
        {
            int n = t >> 1, kq = t & 1;        // 512B rows? 128 n x 2 kq(16B each=8 k)
            // B chunk is 128 n x 32 k fp16 = 8KB = 512 x 16B; 256 threads x 2
#pragma unroll
            for (int q = 0; q < 2; ++q) {
                int idx = q * 256 + t;
                int nn = idx >> 2, kk4 = idx & 3;
                cp16(base + B_H + nn * 80 + kk4 * 16, g_W1h + nn * 256 + c * 32 + kk4 * 8);
            }
            (void)n; (void)kq;
        }
        asm volatile("cp.async.commit_group;" ::: "memory");
    };

    // ---- prologue ----
    lda(0);
    sta(0);
    ldb(0, 0);
    lda(1);
    asm volatile("cp.async.wait_group 0;" ::: "memory");
    __syncthreads();

    for (int c = 0; c < 8; ++c) {
        int s = c & 1;
        if (c < 7) { sta(s ^ 1); ldb(c + 1, s ^ 1); }

        uint32_t ab = sb + 1024 + s * ST_SZ;
#pragma unroll
        for (int kk = 0; kk < 2; ++kk) {
            int k0 = kk * 16;
            int arow = wm * 32 + r8 + (grp & 1) * 8;
            int acol = k0 + (grp >> 1) * 8;
            uint32_t afh[2][4];
#pragma unroll
            for (int mt = 0; mt < 2; ++mt)
                ldsm4(afh[mt], ab + A_H + (arow + mt * 16) * 80 + acol * 2);
#pragma unroll
            for (int ng = 0; ng < 4; ++ng) {
                int nrow = wn * 64 + ng * 16 + r8 + (grp >> 1) * 8;
                int ncol = k0 + (grp & 1) * 8;
                uint32_t bh[4];
                ldsm4(bh, ab + B_H + nrow * 80 + ncol * 2);
#pragma unroll
                for (int mt = 0; mt < 2; ++mt) {
#pragma unroll
                    for (int sub = 0; sub < 2; ++sub)
                        mma16816(d[mt][ng * 2 + sub], afh[mt], bh + 2 * sub);
                }
            }
        }

        if (c < 6) lda(c + 2);
        if (c < 7) asm volatile("cp.async.wait_group 0;" ::: "memory");
        __syncthreads();
    }

    // Epilogue: LeakyReLU, stage tile (stride 130 floats)
#pragma unroll
    for (int mt = 0; mt < 2; ++mt) {
        int rA = wm * 32 + mt * 16 + (lid >> 2);
#pragma unroll
        for (int nt = 0; nt < 8; ++nt) {
            int cc = wn * 64 + nt * 8 + 2 * (lid & 3);
            float x0 = d[mt][nt][0], x1 = d[mt][nt][1];
            float x2 = d[mt][nt][2], x3 = d[mt][nt][3];
            x0 = (x0 >= 0.f) ? x0 : NEG_SLOPE * x0;
            x1 = (x1 >= 0.f) ? x1 : NEG_SLOPE * x1;
            x2 = (x2 >= 0.f) ? x2 : NEG_SLOPE * x2;
            x3 = (x3 >= 0.f) ? x3 : NEG_SLOPE * x3;
            *(float2*)(Os + rA * 130 + cc)       = make_float2(x0, x1);
            *(float2*)(Os + (rA + 8) * 130 + cc) = make_float2(x2, x3);
        }
    }
    __syncthreads();

    // Segmented column-sum + counts (batch sorted -> few runs per tile)
    {
        int col = t & 127, half = t >> 7;
        int rb = half * 64;
        int re = rb + 64; if (re > valid) re = valid;
        if (rb < re) {
            int cur = sbid[rb];
            float acc = 0.f; int cnt = 0;
            for (int r = rb; r < re; ++r) {
                int g = sbid[r];
                if (g != cur) {
                    atomicAdd(&g_hsum[(long long)cur * HH + col], acc);
                    if (col == 0) atomicAdd(&g_counts[cur], (float)cnt);
                    acc = 0.f; cnt = 0; cur = g;
                }
                acc += Os[r * 130 + col];
                cnt++;
            }
            atomicAdd(&g_hsum[(long long)cur * HH + col], acc);
            if (col == 0) atomicAdd(&g_counts[cur], (float)cnt);
        }
    }
}

// out[g,:] = (hsum[g,:]/max(cnt,1)) @ W2 + b2 ; empty graphs -> 0. 16 graphs/block.
__global__ void __launch_bounds__(256)
kernelB(const float* __restrict__ W2, const float* __restrict__ b2,
        float* __restrict__ out, int G)
{
    __shared__ float sh[16][130];   // col 128 = non-empty flag
    int g0 = blockIdx.x * 16;
    int t = threadIdx.x;
    for (int idx = t; idx < 16 * 128; idx += 256) {
        int r = idx >> 7, k = idx & 127;
        int g = g0 + r;
        float val = 0.f, flag = 0.f;
        if (g < G) {
            float cnt = g_counts[g];
            float dn = (cnt < 1.f) ? 1.f : cnt;
            val = g_hsum[(long long)g * HH + k] / dn;
            flag = (cnt >= 0.5f) ? 1.f : 0.f;
        }
        sh[r][k] = val;
        if (k == 0) sh[r][128] = flag;
    }
    __syncthreads();

    int col = t & 127, rg = t >> 7;
    float bv = b2[col];
    float acc[8];
#pragma unroll
    for (int r = 0; r < 8; ++r) acc[r] = bv;
#pragma unroll 4
    for (int k = 0; k < 128; ++k) {
        float w = W2[k * O_DIM + col];
#pragma unroll
        for (int r = 0; r < 8; ++r) acc[r] += sh[rg * 8 + r][k] * w;
    }
#pragma unroll
    for (int r = 0; r < 8; ++r) {
        int g = g0 + rg * 8 + r;
        if (g < G) out[(long long)g * O_DIM + col] = acc[r] * sh[rg * 8 + r][128];
    }
}

extern "C" void kernel_launch(void* const* d_in, const int* in_sizes, int n_in,
                              void* d_out, int out_size)
{
    const float* v     = (const float*)d_in[0];
    const int*   batch = (const int*)d_in[1];
    int w = 2;
    if (n_in >= 7 && in_sizes[2] == 1) w = 3;   // skip num_graphs scalar if present
    const float* W1 = (const float*)d_in[w];
    const float* b1 = (const float*)d_in[w + 1];
    const float* W2 = (const float*)d_in[w + 2];
    const float* b2 = (const float*)d_in[w + 3];

    int N = in_sizes[1];
    int G = out_size / O_DIM;
    int hsumN = G * HH;

    int zn = hsumN; if (zn < G) zn = G; if (zn < 256 * 128) zn = 256 * 128;
    prep_kernel<<<(zn + 255) / 256, 256>>>(W1, hsumN, G);

    static int smem_set = 0;
    if (!smem_set) {
        cudaFuncSetAttribute((const void*)fused1,
                             cudaFuncAttributeMaxDynamicSharedMemorySize, SMEM_BYTES);
        smem_set = 1;
    }
    int nb = (N + 127) / 128;
    fused1<<<nb, 256, SMEM_BYTES>>>(v, batch, b1, N);

    kernelB<<<(G + 15) / 16, 256>>>(W2, b2, (float*)d_out, G);
}

// round 9
// speedup vs baseline: 4.5313x; 1.1872x over previous
#include <cuda_runtime.h>
#include <cuda_fp16.h>
#include <cstdint>

#define NEG_SLOPE 0.015f
#define HH    128
#define O_DIM 128

// Scratch: segment sums [G, HH], per-graph counts, fp16 transposed W1.
__device__ float g_hsum[1 << 21];
__device__ float g_counts[1 << 16];
__device__ __half g_W1h[128 * 256];   // [n][k], k contiguous

static __device__ __forceinline__ uint32_t smem_u32(const void* p) {
    uint32_t a;
    asm("{ .reg .u64 t; cvta.to.shared.u64 t, %1; cvt.u32.u64 %0, t; }" : "=r"(a) : "l"(p));
    return a;
}
static __device__ __forceinline__ void ldsm4(uint32_t* r, uint32_t addr) {
    asm volatile("ldmatrix.sync.aligned.m8n8.x4.shared.b16 {%0,%1,%2,%3}, [%4];"
                 : "=r"(r[0]), "=r"(r[1]), "=r"(r[2]), "=r"(r[3]) : "r"(addr));
}
static __device__ __forceinline__ void mma16816(float* d, const uint32_t* a,
                                                const uint32_t* b) {
    asm volatile("mma.sync.aligned.m16n8k16.row.col.f32.f16.f16.f32 "
                 "{%0,%1,%2,%3}, {%4,%5,%6,%7}, {%8,%9}, {%0,%1,%2,%3};"
                 : "+f"(d[0]), "+f"(d[1]), "+f"(d[2]), "+f"(d[3])
                 : "r"(a[0]), "r"(a[1]), "r"(a[2]), "r"(a[3]), "r"(b[0]), "r"(b[1]));
}
static __device__ __forceinline__ void cp16(uint32_t dst, const void* src) {
    asm volatile("cp.async.cg.shared.global [%0], [%1], 16;" :: "r"(dst), "l"(src));
}
#define CP_COMMIT() asm volatile("cp.async.commit_group;" ::: "memory")
#define CP_WAIT1()  asm volatile("cp.async.wait_group 1;" ::: "memory")

// Zero scratch + W1 -> fp16, transposed to [n][k].
__global__ void prep_kernel(const float* __restrict__ W1, int hsumN, int G) {
    int i = blockIdx.x * blockDim.x + threadIdx.x;
    if (i < hsumN) g_hsum[i] = 0.f;
    if (i < G)     g_counts[i] = 0.f;
    if (i < 256 * 128) {
        int k = i >> 7, n = i & 127;          // W1 is [256][128] row-major
        g_W1h[n * 256 + k] = __float2half_rn(W1[i]);
    }
}

// SMEM (bytes):
//  [0,512)     sbid[128]
//  F32A: 3 slots x 16384  (A fp32 staging, row stride 128B)
//  F16A: 2 slots x 10240  (A fp16, row stride 80B)
//  F16B: 3 slots x 10240  (B fp16, row stride 80B)
//  [1024,..)  reused as Os[128][130] floats in the epilogue
#define F32A  1024
#define F16A  (F32A + 3 * 16384)
#define F16B  (F16A + 2 * 10240)
#define SMEM_BYTES (F16B + 3 * 10240)

extern "C" __global__ void __launch_bounds__(256, 2)
fused1(const float* __restrict__ v, const int* __restrict__ batch,
       const float* __restrict__ b1, int N)
{
    extern __shared__ __align__(128) char smem[];
    int*   sbid = (int*)smem;
    float* Os   = (float*)(smem + 1024);
    uint32_t sb = smem_u32(smem);

    int t = threadIdx.x, lid = t & 31, wid = t >> 5;
    int wm = wid & 3, wn = wid >> 2;          // warp tile: rows wm*32, cols wn*64
    long long r0 = (long long)blockIdx.x * 128;
    int valid = N - (int)r0; if (valid > 128) valid = 128;
    if (t < 128) sbid[t] = (t < valid) ? batch[r0 + t] : -1;

    // Accumulators, bias-initialized. d[mt][nt][0..3]
    float d[2][8][4];
    {
        int cb = wn * 64 + 2 * (lid & 3);
#pragma unroll
        for (int nt = 0; nt < 8; ++nt) {
            float bx = __ldg(b1 + cb + nt * 8);
            float by = __ldg(b1 + cb + nt * 8 + 1);
#pragma unroll
            for (int mt = 0; mt < 2; ++mt) {
                d[mt][nt][0] = bx; d[mt][nt][1] = by;
                d[mt][nt][2] = bx; d[mt][nt][3] = by;
            }
        }
    }

    const float* vb = v + r0 * 256;
    int r8 = lid & 7, grp = lid >> 3;
    int row_a = t >> 1;            // fixed per-thread A mapping pieces
    (void)row_a;

    // cp.async A fp32 chunk ch -> slot
    auto cpA = [&](int ch, int slot) {
        uint32_t base = sb + F32A + slot * 16384;
#pragma unroll
        for (int q = 0; q < 4; ++q) {
            int idx = q * 256 + t, row = idx >> 3, f4 = idx & 7;
            int gr = (row < valid) ? row : (valid - 1);
            cp16(base + row * 128 + f4 * 16, vb + (long long)gr * 256 + ch * 32 + f4 * 4);
        }
    };
    // cp.async B fp16 chunk ch -> slot
    auto cpB = [&](int ch, int slot) {
        uint32_t base = sb + F16B + slot * 10240;
#pragma unroll
        for (int q = 0; q < 2; ++q) {
            int idx = q * 256 + t;
            int nn = idx >> 2, kk4 = idx & 3;
            cp16(base + nn * 80 + kk4 * 16, g_W1h + nn * 256 + ch * 32 + kk4 * 8);
        }
    };
    // convert f32 slot (ch%3) -> f16A slot (ch&1)
    auto convert = [&](int ch) {
        char* src = smem + F32A + (ch % 3) * 16384;
        char* dst = smem + F16A + (ch & 1) * 10240;
#pragma unroll
        for (int q = 0; q < 4; ++q) {
            int idx = q * 256 + t, row = idx >> 3, f4 = idx & 7;
            float4 a = *(const float4*)(src + row * 128 + f4 * 16);
            __half2 h01 = __floats2half2_rn(a.x, a.y);
            __half2 h23 = __floats2half2_rn(a.z, a.w);
            *(uint2*)(dst + row * 80 + f4 * 8) =
                make_uint2(*(uint32_t*)&h01, *(uint32_t*)&h23);
        }
    };

    // ---- prologue ----
    cpA(0, 0); cpA(1, 1); cpB(0, 0); cpB(1, 1); CP_COMMIT();   // P1
    cpA(2, 2); CP_COMMIT();                                     // P2
    CP_WAIT1();            // P1 arrived
    __syncthreads();
    convert(0);            // f16A[0] ready
    __syncthreads();

    for (int c = 0; c < 8; ++c) {
        int s = c & 1;
        if (c < 7) convert(c + 1);                 // f32[(c+1)%3] -> f16A[s^1]
        if (c < 5) cpA(c + 3, (c + 3) % 3);
        if (c < 6) cpB(c + 2, (c + 2) % 3);
        CP_COMMIT();

        uint32_t abA = sb + F16A + s * 10240;
        uint32_t abB = sb + F16B + (c % 3) * 10240;
#pragma unroll
        for (int kk = 0; kk < 2; ++kk) {
            int k0 = kk * 16;
            int arow = wm * 32 + r8 + (grp & 1) * 8;
            int acol = k0 + (grp >> 1) * 8;
            uint32_t afh[2][4];
#pragma unroll
            for (int mt = 0; mt < 2; ++mt)
                ldsm4(afh[mt], abA + (arow + mt * 16) * 80 + acol * 2);
#pragma unroll
            for (int ng = 0; ng < 4; ++ng) {
                int nrow = wn * 64 + ng * 16 + r8 + (grp >> 1) * 8;
                int ncol = k0 + (grp & 1) * 8;
                uint32_t bh[4];
                ldsm4(bh, abB + nrow * 80 + ncol * 2);
#pragma unroll
                for (int mt = 0; mt < 2; ++mt) {
#pragma unroll
                    for (int sub = 0; sub < 2; ++sub)
                        mma16816(d[mt][ng * 2 + sub], afh[mt], bh + 2 * sub);
                }
            }
        }

        CP_WAIT1();        // everything up to group G_{c-1} arrived
        __syncthreads();
    }

    // Epilogue: LeakyReLU, stage tile (stride 130 floats)
#pragma unroll
    for (int mt = 0; mt < 2; ++mt) {
        int rA = wm * 32 + mt * 16 + (lid >> 2);
#pragma unroll
        for (int nt = 0; nt < 8; ++nt) {
            int cc = wn * 64 + nt * 8 + 2 * (lid & 3);
            float x0 = d[mt][nt][0], x1 = d[mt][nt][1];
            float x2 = d[mt][nt][2], x3 = d[mt][nt][3];
            x0 = (x0 >= 0.f) ? x0 : NEG_SLOPE * x0;
            x1 = (x1 >= 0.f) ? x1 : NEG_SLOPE * x1;
            x2 = (x2 >= 0.f) ? x2 : NEG_SLOPE * x2;
            x3 = (x3 >= 0.f) ? x3 : NEG_SLOPE * x3;
            *(float2*)(Os + rA * 130 + cc)       = make_float2(x0, x1);
            *(float2*)(Os + (rA + 8) * 130 + cc) = make_float2(x2, x3);
        }
    }
    __syncthreads();

    // Segmented column-sum + counts (batch sorted -> few runs per tile)
    {
        int col = t & 127, half = t >> 7;
        int rb = half * 64;
        int re = rb + 64; if (re > valid) re = valid;
        if (rb < re) {
            int cur = sbid[rb];
            float acc = 0.f; int cnt = 0;
            for (int r = rb; r < re; ++r) {
                int g = sbid[r];
                if (g != cur) {
                    atomicAdd(&g_hsum[(long long)cur * HH + col], acc);
                    if (col == 0) atomicAdd(&g_counts[cur], (float)cnt);
                    acc = 0.f; cnt = 0; cur = g;
                }
                acc += Os[r * 130 + col];
                cnt++;
            }
            atomicAdd(&g_hsum[(long long)cur * HH + col], acc);
            if (col == 0) atomicAdd(&g_counts[cur], (float)cnt);
        }
    }
}

// out[g,:] = (hsum[g,:]/max(cnt,1)) @ W2 + b2 ; empty graphs -> 0. 16 graphs/block.
__global__ void __launch_bounds__(256)
kernelB(const float* __restrict__ W2, const float* __restrict__ b2,
        float* __restrict__ out, int G)
{
    __shared__ float sh[16][130];   // col 128 = non-empty flag
    int g0 = blockIdx.x * 16;
    int t = threadIdx.x;
    for (int idx = t; idx < 16 * 128; idx += 256) {
        int r = idx >> 7, k = idx & 127;
        int g = g0 + r;
        float val = 0.f, flag = 0.f;
        if (g < G) {
            float cnt = g_counts[g];
            float dn = (cnt < 1.f) ? 1.f : cnt;
            val = g_hsum[(long long)g * HH + k] / dn;
            flag = (cnt >= 0.5f) ? 1.f : 0.f;
        }
        sh[r][k] = val;
        if (k == 0) sh[r][128] = flag;
    }
    __syncthreads();

    int col = t & 127, rg = t >> 7;
    float bv = b2[col];
    float acc[8];
#pragma unroll
    for (int r = 0; r < 8; ++r) acc[r] = bv;
#pragma unroll 4
    for (int k = 0; k < 128; ++k) {
        float w = W2[k * O_DIM + col];
#pragma unroll
        for (int r = 0; r < 8; ++r) acc[r] += sh[rg * 8 + r][k] * w;
    }
#pragma unroll
    for (int r = 0; r < 8; ++r) {
        int g = g0 + rg * 8 + r;
        if (g < G) out[(long long)g * O_DIM + col] = acc[r] * sh[rg * 8 + r][128];
    }
}

extern "C" void kernel_launch(void* const* d_in, const int* in_sizes, int n_in,
                              void* d_out, int out_size)
{
    const float* v     = (const float*)d_in[0];
    const int*   batch = (const int*)d_in[1];
    int w = 2;
    if (n_in >= 7 && in_sizes[2] == 1) w = 3;   // skip num_graphs scalar if present
    const float* W1 = (const float*)d_in[w];
    const float* b1 = (const float*)d_in[w + 1];
    const float* W2 = (const float*)d_in[w + 2];
    const float* b2 = (const float*)d_in[w + 3];

    int N = in_sizes[1];
    int G = out_size / O_DIM;
    int hsumN = G * HH;

    int zn = hsumN; if (zn < G) zn = G; if (zn < 256 * 128) zn = 256 * 128;
    prep_kernel<<<(zn + 255) / 256, 256>>>(W1, hsumN, G);

    static int smem_set = 0;
    if (!smem_set) {
        cudaFuncSetAttribute((const void*)fused1,
                             cudaFuncAttributeMaxDynamicSharedMemorySize, SMEM_BYTES);
        smem_set = 1;
    }
    int nb = (N + 127) / 128;
    fused1<<<nb, 256, SMEM_BYTES>>>(v, batch, b1, N);

    kernelB<<<(G + 15) / 16, 256>>>(W2, b2, (float*)d_out, G);
}